// round 1
// baseline (speedup 1.0000x reference)
#include <cuda_runtime.h>
#include <cstdint>

// Problem constants (fixed by the dataset)
#define BB 4
#define NN 50000
#define RR 100000
#define EE 1600000
#define D1 32
#define D2 16
#define NEG 0.2f

// Bucket capacities (Poisson lambda=16 for R-rows, 32 for N-rows; overflow prob < 1e-30)
#define CAP_T1 128
#define CAP_X1 160
#define CAP_T2 128
#define CAP_P1 256

// ---------------- device scratch (zero-init at module load) ----------------
__device__ float g_h1[BB * NN * D1];   // 25.6 MB  h1 = x @ W1 (dense)
__device__ float g_T1[BB * RR * D1];   // 51.2 MB  layer-1 wavelet rows (sparse-written)
__device__ float g_x1[BB * NN * D1];   // 25.6 MB  layer-1 output (sparse-written)
__device__ float g_h2[BB * NN * D2];   // 12.8 MB  h2 = x1 @ W2 (sparse-written)
__device__ float g_T2[BB * RR * D2];   // 25.6 MB  layer-2 wavelet rows (sparse-written)

__device__ int g_cntT1[RR];
__device__ int g_cntX1[NN];
__device__ int g_cntT2[RR];
__device__ int g_cntP1[2];
__device__ int g_bT1[RR * CAP_T1];     // 51.2 MB
__device__ int g_bX1[NN * CAP_X1];     // 32   MB
__device__ int g_bT2[RR * CAP_T2];     // 51.2 MB
__device__ int g_bP1[2 * CAP_P1];
__device__ unsigned char g_BT2[RR];
__device__ unsigned char g_Bh2[NN];
__device__ unsigned char g_BT1[RR];

// ---------------- reset per call ----------------
__global__ void k_zero() {
    int i = blockIdx.x * blockDim.x + threadIdx.x;
    int stride = gridDim.x * blockDim.x;
    for (int j = i; j < RR; j += stride) {
        g_cntT1[j] = 0; g_cntT2[j] = 0; g_BT2[j] = 0; g_BT1[j] = 0;
    }
    for (int j = i; j < NN; j += stride) {
        g_cntX1[j] = 0; g_Bh2[j] = 0;
    }
    if (i < 2) g_cntP1[i] = 0;
}

// ---------------- backward pruning scans ----------------
// P1: wi-edges landing on the 2 output nodes -> bucket + mark needed T2 rows
__global__ void k_p1(const int* __restrict__ wiRows, const int* __restrict__ wiCols) {
    int e = blockIdx.x * blockDim.x + threadIdx.x;
    if (e >= EE) return;
    int r = wiRows[e];
    if (r >= NN - 2) {
        int s = r - (NN - 2);
        int slot = atomicAdd(&g_cntP1[s], 1);
        if (slot < CAP_P1) g_bP1[s * CAP_P1 + slot] = e;
        g_BT2[wiCols[e]] = 1;
    }
}

// P2: w-edges feeding needed T2 rows -> bucket + mark needed h2 nodes
__global__ void k_p2(const int* __restrict__ wRows, const int* __restrict__ wCols) {
    int e = blockIdx.x * blockDim.x + threadIdx.x;
    if (e >= EE) return;
    int r = wRows[e];
    if (g_BT2[r]) {
        int slot = atomicAdd(&g_cntT2[r], 1);
        if (slot < CAP_T2) g_bT2[r * CAP_T2 + slot] = e;
        g_Bh2[wCols[e]] = 1;
    }
}

// P3: wi-edges feeding needed x1 nodes -> bucket + mark needed T1 rows
__global__ void k_p3(const int* __restrict__ wiRows, const int* __restrict__ wiCols) {
    int e = blockIdx.x * blockDim.x + threadIdx.x;
    if (e >= EE) return;
    int n = wiRows[e];
    if (g_Bh2[n]) {
        int slot = atomicAdd(&g_cntX1[n], 1);
        if (slot < CAP_X1) g_bX1[n * CAP_X1 + slot] = e;
        g_BT1[wiCols[e]] = 1;
    }
}

// P4: w-edges feeding needed T1 rows -> bucket
__global__ void k_p4(const int* __restrict__ wRows, const int* __restrict__ wCols) {
    int e = blockIdx.x * blockDim.x + threadIdx.x;
    if (e >= EE) return;
    int r = wRows[e];
    if (g_BT1[r]) {
        int slot = atomicAdd(&g_cntT1[r], 1);
        if (slot < CAP_T1) g_bT1[r * CAP_T1 + slot] = e;
    }
}

// ---------------- forward compute ----------------
// F0: h1 = x @ W1 for all (b, n). One warp per (b,n) row.
__global__ void k_h1(const float* __restrict__ x, const float* __restrict__ W1) {
    __shared__ float sW[D1 * D1];
    int t = threadIdx.x;
    for (int i = t; i < D1 * D1; i += blockDim.x) sW[i] = W1[i];
    __syncthreads();
    int warp = (blockIdx.x * blockDim.x + t) >> 5;
    int lane = t & 31;
    if (warp >= BB * NN) return;
    float xv = x[warp * D1 + lane];
    float acc = 0.f;
#pragma unroll
    for (int k = 0; k < D1; k++) {
        float xk = __shfl_sync(0xffffffffu, xv, k);
        acc = fmaf(xk, sW[k * D1 + lane], acc);
    }
    g_h1[warp * D1 + lane] = acc;
}

// F1: T1[row] = sum_e w_val[e] * h1[:, w_col[e], :]  (one warp per R-row, all 4 batches)
__global__ void k_T1(const int* __restrict__ wCols, const float* __restrict__ wVals) {
    int warp = (blockIdx.x * blockDim.x + threadIdx.x) >> 5;
    int lane = threadIdx.x & 31;
    if (warp >= RR) return;
    int c = g_cntT1[warp];
    if (c == 0) return;
    if (c > CAP_T1) c = CAP_T1;
    int b = lane >> 3, q = lane & 7;            // 4 batches x 8 float4-chunks = 32 lanes
    float4 acc = make_float4(0.f, 0.f, 0.f, 0.f);
    const int* bucket = g_bT1 + warp * CAP_T1;
    for (int i = 0; i < c; i++) {
        int e = bucket[i];
        int col = wCols[e];
        float v = wVals[e];
        float4 h = *(const float4*)&g_h1[(b * NN + col) * D1 + q * 4];
        acc.x = fmaf(v, h.x, acc.x); acc.y = fmaf(v, h.y, acc.y);
        acc.z = fmaf(v, h.z, acc.z); acc.w = fmaf(v, h.w, acc.w);
    }
    *(float4*)&g_T1[(b * RR + warp) * D1 + q * 4] = acc;
}

// F2: x1[n] = leaky_relu( sum_e wi_val[e]*diag1[col] * T1[:, col, :] )
__global__ void k_x1(const int* __restrict__ wiCols, const float* __restrict__ wiVals,
                     const float* __restrict__ diag1) {
    int warp = (blockIdx.x * blockDim.x + threadIdx.x) >> 5;
    int lane = threadIdx.x & 31;
    if (warp >= NN) return;
    int c = g_cntX1[warp];
    if (c == 0) return;
    if (c > CAP_X1) c = CAP_X1;
    int b = lane >> 3, q = lane & 7;
    float4 acc = make_float4(0.f, 0.f, 0.f, 0.f);
    const int* bucket = g_bX1 + warp * CAP_X1;
    for (int i = 0; i < c; i++) {
        int e = bucket[i];
        int col = wiCols[e];
        float coef = wiVals[e] * diag1[col];
        float4 tv = *(const float4*)&g_T1[(b * RR + col) * D1 + q * 4];
        acc.x = fmaf(coef, tv.x, acc.x); acc.y = fmaf(coef, tv.y, acc.y);
        acc.z = fmaf(coef, tv.z, acc.z); acc.w = fmaf(coef, tv.w, acc.w);
    }
    acc.x = acc.x > 0.f ? acc.x : NEG * acc.x;
    acc.y = acc.y > 0.f ? acc.y : NEG * acc.y;
    acc.z = acc.z > 0.f ? acc.z : NEG * acc.z;
    acc.w = acc.w > 0.f ? acc.w : NEG * acc.w;
    *(float4*)&g_x1[(b * NN + warp) * D1 + q * 4] = acc;
}

// F3: h2 = x1 @ W2 at needed nodes only. One warp per node (4 batches, 16 outputs each).
__global__ void k_h2(const float* __restrict__ W2) {
    __shared__ float sW[D1 * D2];
    int t = threadIdx.x;
    for (int i = t; i < D1 * D2; i += blockDim.x) sW[i] = W2[i];
    __syncthreads();
    int warp = (blockIdx.x * blockDim.x + t) >> 5;
    int lane = t & 31;
    if (warp >= NN) return;
    if (g_cntX1[warp] == 0) return;
    int b = lane >> 3, j = lane & 7;
    const float* xr = &g_x1[(b * NN + warp) * D1];
    float a0 = 0.f, a1 = 0.f;
#pragma unroll
    for (int k = 0; k < D1; k++) {
        float xv = xr[k];
        a0 = fmaf(xv, sW[k * D2 + j], a0);
        a1 = fmaf(xv, sW[k * D2 + j + 8], a1);
    }
    g_h2[(b * NN + warp) * D2 + j] = a0;
    g_h2[(b * NN + warp) * D2 + j + 8] = a1;
}

// F4: T2[row] = sum_e w_val[e] * h2[:, col, :]  (one warp per R-row; 16 lanes used)
__global__ void k_T2(const int* __restrict__ wCols, const float* __restrict__ wVals) {
    int warp = (blockIdx.x * blockDim.x + threadIdx.x) >> 5;
    int lane = threadIdx.x & 31;
    if (warp >= RR) return;
    int c = g_cntT2[warp];
    if (c == 0) return;
    if (c > CAP_T2) c = CAP_T2;
    if (lane >= 16) return;
    int b = lane >> 2, q = lane & 3;            // 4 batches x 4 float4-chunks = 16 lanes
    float4 acc = make_float4(0.f, 0.f, 0.f, 0.f);
    const int* bucket = g_bT2 + warp * CAP_T2;
    for (int i = 0; i < c; i++) {
        int e = bucket[i];
        int col = wCols[e];
        float v = wVals[e];
        float4 h = *(const float4*)&g_h2[(b * NN + col) * D2 + q * 4];
        acc.x = fmaf(v, h.x, acc.x); acc.y = fmaf(v, h.y, acc.y);
        acc.z = fmaf(v, h.z, acc.z); acc.w = fmaf(v, h.w, acc.w);
    }
    *(float4*)&g_T2[(b * RR + warp) * D2 + q * 4] = acc;
}

// F5: final 2 nodes -> leaky_relu -> linear heads -> out (B,2,1)
__global__ void k_out(const int* __restrict__ wiCols, const float* __restrict__ wiVals,
                      const float* __restrict__ diag2,
                      const float* __restrict__ rw1, const float* __restrict__ rb1,
                      const float* __restrict__ rw2, const float* __restrict__ rb2,
                      float* __restrict__ out) {
    int warp = threadIdx.x >> 5;   // 8 warps: b = warp&3, s = warp>>2 (s=0 -> node N-2)
    int lane = threadIdx.x & 31;
    int b = warp & 3, s = warp >> 2;
    int c = g_cntP1[s];
    if (c > CAP_P1) c = CAP_P1;
    float acc = 0.f;
    for (int i = 0; i < c; i++) {
        int e = g_bP1[s * CAP_P1 + i];
        int col = wiCols[e];
        float coef = wiVals[e] * diag2[col];
        if (lane < D2) acc = fmaf(coef, g_T2[(b * RR + col) * D2 + lane], acc);
    }
    float v = acc > 0.f ? acc : NEG * acc;
    const float* w = s ? rw2 : rw1;
    float y = (lane < D2) ? v * w[lane] : 0.f;
#pragma unroll
    for (int o = 16; o > 0; o >>= 1) y += __shfl_xor_sync(0xffffffffu, y, o);
    if (lane == 0) out[b * 2 + s] = y + (s ? rb2[0] : rb1[0]);
}

// ---------------- launch ----------------
extern "C" void kernel_launch(void* const* d_in, const int* in_sizes, int n_in,
                              void* d_out, int out_size) {
    const int*   wIdx   = (const int*)d_in[0];
    const float* wVal   = (const float*)d_in[1];
    const int*   wiIdx  = (const int*)d_in[2];
    const float* wiVal  = (const float*)d_in[3];
    const float* x      = (const float*)d_in[4];
    const float* W1     = (const float*)d_in[5];
    const float* diag1  = (const float*)d_in[6];
    const float* W2     = (const float*)d_in[7];
    const float* diag2  = (const float*)d_in[8];
    const float* rw1    = (const float*)d_in[9];
    const float* rb1    = (const float*)d_in[10];
    const float* rw2    = (const float*)d_in[11];
    const float* rb2    = (const float*)d_in[12];

    const int* wRows  = wIdx;
    const int* wCols  = wIdx + EE;
    const int* wiRows = wiIdx;
    const int* wiCols = wiIdx + EE;
    float* out = (float*)d_out;

    const int eBlocks = (EE + 255) / 256;

    k_zero<<<256, 256>>>();
    k_p1<<<eBlocks, 256>>>(wiRows, wiCols);
    k_p2<<<eBlocks, 256>>>(wRows, wCols);
    k_p3<<<eBlocks, 256>>>(wiRows, wiCols);
    k_p4<<<eBlocks, 256>>>(wRows, wCols);
    k_h1<<<(BB * NN * 32) / 256, 256>>>(x, W1);
    k_T1<<<(RR * 32) / 256, 256>>>(wCols, wVal);
    k_x1<<<(NN * 32) / 256, 256>>>(wiCols, wiVal, diag1);
    k_h2<<<(NN * 32) / 256, 256>>>(W2);
    k_T2<<<(RR * 32) / 256, 256>>>(wCols, wVal);
    k_out<<<1, 256>>>(wiCols, wiVal, diag2, rw1, rb1, rw2, rb2, out);
}

// round 2
// speedup vs baseline: 1.2677x; 1.2677x over previous
#include <cuda_runtime.h>
#include <cstdint>

// Problem constants (fixed by the dataset)
#define BB 4
#define NN 50000
#define RR 100000
#define EE 1600000
#define D1 32
#define D2 16
#define NEG 0.2f

// Bucket capacities (Poisson lambda=16 R-rows / 32 N-rows; overflow prob < 1e-25)
#define CAP_T1 128
#define CAP_X1 192
#define CAP_T2 128
#define CAP_P1 256

#define MW_R ((RR + 31) / 32)
#define MW_N ((NN + 31) / 32)

// ---------------- device scratch ----------------
// layouts: [node][batch][d] so one edge-gather touches one contiguous region
__device__ float g_h1[NN * BB * D1];   // 25.6 MB
__device__ float g_T1[RR * BB * D1];   // 51.2 MB
__device__ float g_x1[NN * BB * D1];   // 25.6 MB
__device__ float g_h2[NN * BB * D2];   // 12.8 MB
__device__ float g_T2[RR * BB * D2];   // 25.6 MB

__device__ int  g_cntT1[RR], g_cntX1[NN], g_cntT2[RR], g_cntP1[2];
__device__ int2 g_bT1[RR * CAP_T1];    // (col, val)   102 MB
__device__ int2 g_bX1[NN * CAP_X1];    // (col, coef)   77 MB
__device__ int2 g_bT2[RR * CAP_T2];    // (col, val)   102 MB
__device__ int2 g_bP1[2 * CAP_P1];     // (col, coef)

__device__ unsigned g_mT1[MW_R], g_mT2[MW_R], g_mH2[MW_N];   // bit flags (L1-resident)
__device__ int g_listT1[RR], g_listX1[NN], g_listT2[RR];
__device__ int g_nT1, g_nX1, g_nT2;

// ---------------- reset per call ----------------
__global__ void k_zero() {
    int i = blockIdx.x * blockDim.x + threadIdx.x;
    int stride = gridDim.x * blockDim.x;
    for (int j = i; j < RR; j += stride) { g_cntT1[j] = 0; g_cntT2[j] = 0; }
    for (int j = i; j < NN; j += stride) g_cntX1[j] = 0;
    for (int j = i; j < MW_R; j += stride) { g_mT1[j] = 0u; g_mT2[j] = 0u; }
    for (int j = i; j < MW_N; j += stride) g_mH2[j] = 0u;
    if (i < 2) g_cntP1[i] = 0;
    if (i == 0) { g_nT1 = 0; g_nX1 = 0; g_nT2 = 0; }
}

// ---------------- backward pruning scans (4 edges / thread via int4) ----------------
__global__ void k_p1(const int* __restrict__ wiRows, const int* __restrict__ wiCols,
                     const float* __restrict__ wiVals, const float* __restrict__ diag2) {
    int i = blockIdx.x * blockDim.x + threadIdx.x;
    if (i >= EE / 4) return;
    int4 r4 = ((const int4*)wiRows)[i];
    int e = i * 4;
    int rs[4] = {r4.x, r4.y, r4.z, r4.w};
#pragma unroll
    for (int j = 0; j < 4; j++) {
        int r = rs[j];
        if (r >= NN - 2) {
            int s = r - (NN - 2);
            int col = wiCols[e + j];
            float coef = wiVals[e + j] * diag2[col];
            int slot = atomicAdd(&g_cntP1[s], 1);
            if (slot < CAP_P1) g_bP1[s * CAP_P1 + slot] = make_int2(col, __float_as_int(coef));
            atomicOr(&g_mT2[col >> 5], 1u << (col & 31));
        }
    }
}

__global__ void k_p2(const int* __restrict__ wRows, const int* __restrict__ wCols,
                     const float* __restrict__ wVals) {
    int i = blockIdx.x * blockDim.x + threadIdx.x;
    if (i >= EE / 4) return;
    int4 r4 = ((const int4*)wRows)[i];
    int e = i * 4;
    int rs[4] = {r4.x, r4.y, r4.z, r4.w};
#pragma unroll
    for (int j = 0; j < 4; j++) {
        int r = rs[j];
        if ((g_mT2[r >> 5] >> (r & 31)) & 1u) {
            int col = wCols[e + j];
            int slot = atomicAdd(&g_cntT2[r], 1);
            if (slot == 0) g_listT2[atomicAdd(&g_nT2, 1)] = r;
            if (slot < CAP_T2)
                g_bT2[r * CAP_T2 + slot] = make_int2(col, __float_as_int(wVals[e + j]));
            atomicOr(&g_mH2[col >> 5], 1u << (col & 31));
        }
    }
}

__global__ void k_p3(const int* __restrict__ wiRows, const int* __restrict__ wiCols,
                     const float* __restrict__ wiVals, const float* __restrict__ diag1) {
    int i = blockIdx.x * blockDim.x + threadIdx.x;
    if (i >= EE / 4) return;
    int4 r4 = ((const int4*)wiRows)[i];
    int e = i * 4;
    int rs[4] = {r4.x, r4.y, r4.z, r4.w};
#pragma unroll
    for (int j = 0; j < 4; j++) {
        int r = rs[j];
        if ((g_mH2[r >> 5] >> (r & 31)) & 1u) {
            int col = wiCols[e + j];
            float coef = wiVals[e + j] * diag1[col];
            int slot = atomicAdd(&g_cntX1[r], 1);
            if (slot == 0) g_listX1[atomicAdd(&g_nX1, 1)] = r;
            if (slot < CAP_X1)
                g_bX1[r * CAP_X1 + slot] = make_int2(col, __float_as_int(coef));
            atomicOr(&g_mT1[col >> 5], 1u << (col & 31));
        }
    }
}

__global__ void k_p4(const int* __restrict__ wRows, const int* __restrict__ wCols,
                     const float* __restrict__ wVals) {
    int i = blockIdx.x * blockDim.x + threadIdx.x;
    if (i >= EE / 4) return;
    int4 r4 = ((const int4*)wRows)[i];
    int e = i * 4;
    int rs[4] = {r4.x, r4.y, r4.z, r4.w};
#pragma unroll
    for (int j = 0; j < 4; j++) {
        int r = rs[j];
        if ((g_mT1[r >> 5] >> (r & 31)) & 1u) {
            int slot = atomicAdd(&g_cntT1[r], 1);
            if (slot == 0) g_listT1[atomicAdd(&g_nT1, 1)] = r;
            if (slot < CAP_T1)
                g_bT1[r * CAP_T1 + slot] = make_int2(wCols[e + j], __float_as_int(wVals[e + j]));
        }
    }
}

// ---------------- forward compute ----------------
// h1 = x @ W1, dense, layout [n][b][32]. One warp per (n,b).
__global__ void k_h1(const float* __restrict__ x, const float* __restrict__ W1) {
    __shared__ float sW[D1 * D1];
    int t = threadIdx.x;
    for (int i = t; i < D1 * D1; i += blockDim.x) sW[i] = W1[i];
    __syncthreads();
    int w = (blockIdx.x * blockDim.x + t) >> 5;
    int lane = t & 31;
    if (w >= NN * BB) return;
    int n = w >> 2, b = w & 3;
    float xv = x[((size_t)b * NN + n) * D1 + lane];
    float acc = 0.f;
#pragma unroll
    for (int k = 0; k < D1; k++) {
        float xk = __shfl_sync(0xffffffffu, xv, k);
        acc = fmaf(xk, sW[k * D1 + lane], acc);
    }
    g_h1[(size_t)w * D1 + lane] = acc;
}

// T1[row] = sum_e v_e * h1[col_e]. One warp per active row; grid-stride over list.
__global__ void k_T1() {
    int lane = threadIdx.x & 31;
    int gw = (blockIdx.x * blockDim.x + threadIdx.x) >> 5;
    int nw = (gridDim.x * blockDim.x) >> 5;
    int b = lane >> 3, q = lane & 7;
    int nact = g_nT1;
    for (int i = gw; i < nact; i += nw) {
        int row = g_listT1[i];
        int c = g_cntT1[row]; if (c > CAP_T1) c = CAP_T1;
        const int2* bk = &g_bT1[row * CAP_T1];
        float4 acc = make_float4(0.f, 0.f, 0.f, 0.f);
        int k = 0;
        for (; k + 4 <= c; k += 4) {
            int2 e0 = __ldg(&bk[k]),     e1 = __ldg(&bk[k + 1]);
            int2 e2 = __ldg(&bk[k + 2]), e3 = __ldg(&bk[k + 3]);
            float4 h0 = *(const float4*)&g_h1[((size_t)e0.x * BB + b) * D1 + q * 4];
            float4 h1v = *(const float4*)&g_h1[((size_t)e1.x * BB + b) * D1 + q * 4];
            float4 h2v = *(const float4*)&g_h1[((size_t)e2.x * BB + b) * D1 + q * 4];
            float4 h3v = *(const float4*)&g_h1[((size_t)e3.x * BB + b) * D1 + q * 4];
            float v0 = __int_as_float(e0.y), v1 = __int_as_float(e1.y);
            float v2 = __int_as_float(e2.y), v3 = __int_as_float(e3.y);
            acc.x = fmaf(v0, h0.x, acc.x); acc.y = fmaf(v0, h0.y, acc.y);
            acc.z = fmaf(v0, h0.z, acc.z); acc.w = fmaf(v0, h0.w, acc.w);
            acc.x = fmaf(v1, h1v.x, acc.x); acc.y = fmaf(v1, h1v.y, acc.y);
            acc.z = fmaf(v1, h1v.z, acc.z); acc.w = fmaf(v1, h1v.w, acc.w);
            acc.x = fmaf(v2, h2v.x, acc.x); acc.y = fmaf(v2, h2v.y, acc.y);
            acc.z = fmaf(v2, h2v.z, acc.z); acc.w = fmaf(v2, h2v.w, acc.w);
            acc.x = fmaf(v3, h3v.x, acc.x); acc.y = fmaf(v3, h3v.y, acc.y);
            acc.z = fmaf(v3, h3v.z, acc.z); acc.w = fmaf(v3, h3v.w, acc.w);
        }
        for (; k < c; k++) {
            int2 e0 = __ldg(&bk[k]);
            float v = __int_as_float(e0.y);
            float4 h = *(const float4*)&g_h1[((size_t)e0.x * BB + b) * D1 + q * 4];
            acc.x = fmaf(v, h.x, acc.x); acc.y = fmaf(v, h.y, acc.y);
            acc.z = fmaf(v, h.z, acc.z); acc.w = fmaf(v, h.w, acc.w);
        }
        *(float4*)&g_T1[((size_t)row * BB + b) * D1 + q * 4] = acc;
    }
}

// x1[n] = leaky( sum_e coef_e * T1[col_e] ). One warp per active node.
__global__ void k_x1() {
    int lane = threadIdx.x & 31;
    int gw = (blockIdx.x * blockDim.x + threadIdx.x) >> 5;
    int nw = (gridDim.x * blockDim.x) >> 5;
    int b = lane >> 3, q = lane & 7;
    int nact = g_nX1;
    for (int i = gw; i < nact; i += nw) {
        int node = g_listX1[i];
        int c = g_cntX1[node]; if (c > CAP_X1) c = CAP_X1;
        const int2* bk = &g_bX1[node * CAP_X1];
        float4 acc = make_float4(0.f, 0.f, 0.f, 0.f);
        int k = 0;
        for (; k + 2 <= c; k += 2) {
            int2 e0 = __ldg(&bk[k]), e1 = __ldg(&bk[k + 1]);
            float4 t0 = *(const float4*)&g_T1[((size_t)e0.x * BB + b) * D1 + q * 4];
            float4 t1 = *(const float4*)&g_T1[((size_t)e1.x * BB + b) * D1 + q * 4];
            float v0 = __int_as_float(e0.y), v1 = __int_as_float(e1.y);
            acc.x = fmaf(v0, t0.x, acc.x); acc.y = fmaf(v0, t0.y, acc.y);
            acc.z = fmaf(v0, t0.z, acc.z); acc.w = fmaf(v0, t0.w, acc.w);
            acc.x = fmaf(v1, t1.x, acc.x); acc.y = fmaf(v1, t1.y, acc.y);
            acc.z = fmaf(v1, t1.z, acc.z); acc.w = fmaf(v1, t1.w, acc.w);
        }
        for (; k < c; k++) {
            int2 e0 = __ldg(&bk[k]);
            float v = __int_as_float(e0.y);
            float4 t = *(const float4*)&g_T1[((size_t)e0.x * BB + b) * D1 + q * 4];
            acc.x = fmaf(v, t.x, acc.x); acc.y = fmaf(v, t.y, acc.y);
            acc.z = fmaf(v, t.z, acc.z); acc.w = fmaf(v, t.w, acc.w);
        }
        acc.x = acc.x > 0.f ? acc.x : NEG * acc.x;
        acc.y = acc.y > 0.f ? acc.y : NEG * acc.y;
        acc.z = acc.z > 0.f ? acc.z : NEG * acc.z;
        acc.w = acc.w > 0.f ? acc.w : NEG * acc.w;
        *(float4*)&g_x1[((size_t)node * BB + b) * D1 + q * 4] = acc;
    }
}

// h2 = x1 @ W2 at active nodes. One warp per node (4 batches x 8 lanes -> 16 outputs).
__global__ void k_h2(const float* __restrict__ W2) {
    __shared__ float sW[D1 * D2];
    int t = threadIdx.x;
    for (int i = t; i < D1 * D2; i += blockDim.x) sW[i] = W2[i];
    __syncthreads();
    int lane = t & 31;
    int gw = (blockIdx.x * blockDim.x + t) >> 5;
    int nw = (gridDim.x * blockDim.x) >> 5;
    int b = lane >> 3, j = lane & 7;
    int nact = g_nX1;
    for (int i = gw; i < nact; i += nw) {
        int node = g_listX1[i];
        const float* xr = &g_x1[((size_t)node * BB + b) * D1];
        float a0 = 0.f, a1 = 0.f;
#pragma unroll
        for (int k = 0; k < D1; k++) {
            float xv = xr[k];
            a0 = fmaf(xv, sW[k * D2 + j], a0);
            a1 = fmaf(xv, sW[k * D2 + j + 8], a1);
        }
        g_h2[((size_t)node * BB + b) * D2 + j] = a0;
        g_h2[((size_t)node * BB + b) * D2 + j + 8] = a1;
    }
}

// T2[row] = sum_e v_e * h2[col_e]. One warp per active row (16 lanes).
__global__ void k_T2() {
    int lane = threadIdx.x & 31;
    int gw = (blockIdx.x * blockDim.x + threadIdx.x) >> 5;
    int nw = (gridDim.x * blockDim.x) >> 5;
    int nact = g_nT2;
    int b = (lane >> 2) & 3, q = lane & 3;
    for (int i = gw; i < nact; i += nw) {
        int row = g_listT2[i];
        int c = g_cntT2[row]; if (c > CAP_T2) c = CAP_T2;
        if (lane >= 16) continue;
        const int2* bk = &g_bT2[row * CAP_T2];
        float4 acc = make_float4(0.f, 0.f, 0.f, 0.f);
        for (int k = 0; k < c; k++) {
            int2 e0 = __ldg(&bk[k]);
            float v = __int_as_float(e0.y);
            float4 h = *(const float4*)&g_h2[((size_t)e0.x * BB + b) * D2 + q * 4];
            acc.x = fmaf(v, h.x, acc.x); acc.y = fmaf(v, h.y, acc.y);
            acc.z = fmaf(v, h.z, acc.z); acc.w = fmaf(v, h.w, acc.w);
        }
        *(float4*)&g_T2[((size_t)row * BB + b) * D2 + q * 4] = acc;
    }
}

// final: 2 nodes -> leaky -> linear heads -> out (B,2,1)
__global__ void k_out(const float* __restrict__ rw1, const float* __restrict__ rb1,
                      const float* __restrict__ rw2, const float* __restrict__ rb2,
                      float* __restrict__ out) {
    int warp = threadIdx.x >> 5;   // 8 warps: b = warp&3, s = warp>>2
    int lane = threadIdx.x & 31;
    int b = warp & 3, s = warp >> 2;
    int c = g_cntP1[s]; if (c > CAP_P1) c = CAP_P1;
    float acc = 0.f;
    for (int i = 0; i < c; i++) {
        int2 e = g_bP1[s * CAP_P1 + i];
        float coef = __int_as_float(e.y);
        if (lane < D2) acc = fmaf(coef, g_T2[((size_t)e.x * BB + b) * D2 + lane], acc);
    }
    float v = acc > 0.f ? acc : NEG * acc;
    const float* w = s ? rw2 : rw1;
    float y = (lane < D2) ? v * w[lane] : 0.f;
#pragma unroll
    for (int o = 16; o > 0; o >>= 1) y += __shfl_xor_sync(0xffffffffu, y, o);
    if (lane == 0) out[b * 2 + s] = y + (s ? rb2[0] : rb1[0]);
}

// ---------------- launch ----------------
extern "C" void kernel_launch(void* const* d_in, const int* in_sizes, int n_in,
                              void* d_out, int out_size) {
    const int*   wIdx   = (const int*)d_in[0];
    const float* wVal   = (const float*)d_in[1];
    const int*   wiIdx  = (const int*)d_in[2];
    const float* wiVal  = (const float*)d_in[3];
    const float* x      = (const float*)d_in[4];
    const float* W1     = (const float*)d_in[5];
    const float* diag1  = (const float*)d_in[6];
    const float* W2     = (const float*)d_in[7];
    const float* diag2  = (const float*)d_in[8];
    const float* rw1    = (const float*)d_in[9];
    const float* rb1    = (const float*)d_in[10];
    const float* rw2    = (const float*)d_in[11];
    const float* rb2    = (const float*)d_in[12];

    const int* wRows  = wIdx;
    const int* wCols  = wIdx + EE;
    const int* wiRows = wiIdx;
    const int* wiCols = wiIdx + EE;
    float* out = (float*)d_out;

    const int sBlocks = (EE / 4 + 255) / 256;

    k_zero<<<256, 256>>>();
    k_p1<<<sBlocks, 256>>>(wiRows, wiCols, wiVal, diag2);
    k_p2<<<sBlocks, 256>>>(wRows, wCols, wVal);
    k_p3<<<sBlocks, 256>>>(wiRows, wiCols, wiVal, diag1);
    k_p4<<<sBlocks, 256>>>(wRows, wCols, wVal);
    k_h1<<<(NN * BB * 32 + 255) / 256, 256>>>(x, W1);
    k_T1<<<1024, 256>>>();
    k_x1<<<64, 256>>>();
    k_h2<<<64, 256>>>(W2);
    k_T2<<<16, 256>>>();
    k_out<<<1, 256>>>(rw1, rb1, rw2, rb2, out);
}